// round 12
// baseline (speedup 1.0000x reference)
#include <cuda_runtime.h>
#include <cuda_bf16.h>
#include <cstdint>

#define BB 64
#define TT 512
#define HH 300
#define VV 50257

// ---- packed fp32x2 helpers (sm_103a FFMA2; only reachable via PTX) ----
#define FMA_F32X2(acc, a, b) \
    asm("fma.rn.f32x2 %0, %1, %2, %3;" : "=l"(acc) : "l"(a), "l"(b), "l"(acc))
#define PACK_F32X2(out, lo, hi) \
    asm("mov.b64 %0, {%1, %2};" : "=l"(out) : "f"(lo), "f"(hi))
#define UNPACK_F32X2(lo, hi, in) \
    asm("mov.b64 {%0, %1}, %2;" : "=f"(lo), "=f"(hi) : "l"(in))

typedef unsigned long long u64;

__device__ __forceinline__ u64 d2u_lo(const double2& d) {
    return __double_as_longlong(d.x);
}
__device__ __forceinline__ u64 d2u_hi(const double2& d) {
    return __double_as_longlong(d.y);
}

// Scratch (allocation-free: __device__ globals)
__device__ float g_ux[BB * TT * HH];   // [B*T, H] input projections
__device__ float g_h[BB * HH];         // final hidden state

// =====================================================================
// Kernel 1: ux[m, g] = sum_h emb[tokens[m]][h] * U[g][h]
// Tiled SGEMM with gather. CTA tile: 128 m x 128 g, Tk = 8.
// Double-buffered smem, ONE __syncthreads per k-iter, fp32x2 packed FMA.
// g-tiles overlap (g0 = 0,128,172) so N=300 is covered with dense tiles.
// =====================================================================
__global__ void __launch_bounds__(256) k_embed_ux(
    const int* __restrict__ tokens, const float* __restrict__ emb,
    const float* __restrict__ U)
{
    __shared__ int ts[128];
    __shared__ __align__(16) float xs[2][8][132];   // xs[buf][k][m]
    __shared__ __align__(16) float us[2][8][132];   // us[buf][k][g]

    const int t  = threadIdx.x;
    const int m0 = blockIdx.x * 128;
    const int g0 = (blockIdx.y < 2) ? blockIdx.y * 128 : (HH - 128); // 0,128,172

    if (t < 128) ts[t] = tokens[m0 + t];
    __syncthreads();

    u64 acc2[8][4];    // [m_i][g_pair]  (each u64 = 2 packed fp32 accums)
#pragma unroll
    for (int i = 0; i < 8; i++)
#pragma unroll
        for (int p = 0; p < 4; p++) acc2[i][p] = 0ull;

    const int lm   = t & 127;      // loader row
    const int part = t >> 7;       // loader k-half (0/1)
    const int tx   = t & 15;       // compute g-group
    const int ty   = t >> 4;       // compute m-group

    const size_t erow = (size_t)ts[lm] * HH;
    const size_t urow = (size_t)(g0 + lm) * HH;

    const int NIT = 38;            // ceil(300/8)

    float4 xv, uv;
    {
        const int kk = part * 4;
        xv = *(const float4*)(emb + erow + kk);
        uv = *(const float4*)(U   + urow + kk);
        xs[0][part*4+0][lm] = xv.x; xs[0][part*4+1][lm] = xv.y;
        xs[0][part*4+2][lm] = xv.z; xs[0][part*4+3][lm] = xv.w;
        us[0][part*4+0][lm] = uv.x; us[0][part*4+1][lm] = uv.y;
        us[0][part*4+2][lm] = uv.z; us[0][part*4+3][lm] = uv.w;
    }

    for (int it = 0; it < NIT; it++) {
        __syncthreads();   // buf[it&1] stores visible; prior readers done

        if (it + 1 < NIT) {
            const int kk = (it + 1) * 8 + part * 4;
            if (kk <= HH - 4) {
                xv = *(const float4*)(emb + erow + kk);
                uv = *(const float4*)(U   + urow + kk);
            } else {
                xv = make_float4(0.f,0.f,0.f,0.f);
                uv = make_float4(0.f,0.f,0.f,0.f);
            }
        }

        const int cb = it & 1;
#pragma unroll
        for (int k = 0; k < 8; k++) {
            float4 a0 = *(const float4*)&xs[cb][k][ty * 8];
            float4 a1 = *(const float4*)&xs[cb][k][ty * 8 + 4];
            double2 uA = *(const double2*)&us[cb][k][tx * 8];      // pairs 0,1
            double2 uB = *(const double2*)&us[cb][k][tx * 8 + 4];  // pairs 2,3
            const u64 up[4] = { d2u_lo(uA), d2u_hi(uA), d2u_lo(uB), d2u_hi(uB) };
            float xr[8] = {a0.x, a0.y, a0.z, a0.w, a1.x, a1.y, a1.z, a1.w};
#pragma unroll
            for (int i = 0; i < 8; i++) {
                u64 xd;
                PACK_F32X2(xd, xr[i], xr[i]);
#pragma unroll
                for (int p = 0; p < 4; p++)
                    FMA_F32X2(acc2[i][p], xd, up[p]);
            }
        }

        if (it + 1 < NIT) {
            const int nb = (it + 1) & 1;
            xs[nb][part*4+0][lm] = xv.x; xs[nb][part*4+1][lm] = xv.y;
            xs[nb][part*4+2][lm] = xv.z; xs[nb][part*4+3][lm] = xv.w;
            us[nb][part*4+0][lm] = uv.x; us[nb][part*4+1][lm] = uv.y;
            us[nb][part*4+2][lm] = uv.z; us[nb][part*4+3][lm] = uv.w;
        }
    }

    // Epilogue (all in-bounds by tile overlap)
#pragma unroll
    for (int i = 0; i < 8; i++) {
        const int m = m0 + ty * 8 + i;
#pragma unroll
        for (int p = 0; p < 4; p += 2) {
            float e0, e1, e2, e3;
            UNPACK_F32X2(e0, e1, acc2[i][p]);
            UNPACK_F32X2(e2, e3, acc2[i][p + 1]);
            const int g = g0 + tx * 8 + p * 2;
            *(float4*)(g_ux + (size_t)m * HH + g) = make_float4(e0, e1, e2, e3);
        }
    }
}

// =====================================================================
// Kernel 2: recurrence.  2-CTA cluster per batch element (R6 protocol,
// byte-identical sync skeleton; only the dot products are fp32x2-packed).
// Rank 0 owns rows [0,152), rank 1 owns [152,300).  W half in registers
// (76 packed u64 per thread = 152 fp32).  Per step: Phase A (local
// k-range dot), acquire-poll on single monotonic DSMEM flag, Phase B
// (peer k-range dot), tanhf, half==0 lane stores local + remote copies,
// __syncthreads, elected st.release.cluster of peer flag.
// =====================================================================
__global__ void __launch_bounds__(320, 1) __cluster_dims__(2, 1, 1)
k_scan(const float* __restrict__ W, const float* __restrict__ ihs)
{
    __shared__ __align__(16) float hbuf[2][304];
    __shared__ unsigned int flag;      // peer-written step counter

    const int t    = threadIdx.x;
    const int r    = blockIdx.x & 1;
    const int b    = blockIdx.x >> 1;
    const int o_l  = t >> 1;
    const int half = t & 1;

    const int Lb     = r ? 152 : 0;    // local row/k-range base
    const int Pb     = r ? 0 : 152;    // peer  row/k-range base
    const int myLen  = r ? 148 : 152;
    const bool active = (o_l < myLen);
    const int o_g    = Lb + o_l;       // global output row

    const int wLbase = Lb + half * 76; // 16B-aligned float4 bases
    const int wPbase = Pb + half * 76;

    // W slices into PACKED registers: 38+38 u64 (=152 fp32 coefficients)
    u64 wl2[38], wp2[38];
#pragma unroll
    for (int j = 0; j < 38; j++) {
        const int kL = wLbase + 2 * j;
        const int kP = wPbase + 2 * j;
        float l0 = (active && kL     < HH) ? W[(size_t)o_g * HH + kL]     : 0.f;
        float l1 = (active && kL + 1 < HH) ? W[(size_t)o_g * HH + kL + 1] : 0.f;
        float p0 = (active && kP     < HH) ? W[(size_t)o_g * HH + kP]     : 0.f;
        float p1 = (active && kP + 1 < HH) ? W[(size_t)o_g * HH + kP + 1] : 0.f;
        PACK_F32X2(wl2[j], l0, l1);
        PACK_F32X2(wp2[j], p0, p1);
    }

    // Init h buffers (pad region stays 0 forever) and flag
    if (t < 304) {
        hbuf[0][t] = (t < HH) ? ihs[b * HH + t] : 0.f;
        hbuf[1][t] = 0.f;
    }
    if (t == 0) flag = 0u;

    // Local / peer addresses
    uint32_t my_h0, my_fl;
    {
        uint64_t a;
        asm("cvta.to.shared.u64 %0, %1;" : "=l"(a) : "l"(&hbuf[0][0]));
        my_h0 = (uint32_t)a;
        asm("cvta.to.shared.u64 %0, %1;" : "=l"(a) : "l"(&flag));
        my_fl = (uint32_t)a;
    }
    uint32_t ph0, pfl;
    asm("mapa.shared::cluster.u32 %0, %1, %2;" : "=r"(ph0) : "r"(my_h0), "r"(r ^ 1));
    asm("mapa.shared::cluster.u32 %0, %1, %2;" : "=r"(pfl) : "r"(my_fl), "r"(r ^ 1));
    const uint32_t pdst0 = ph0 + (uint32_t)o_g * 4u;             // peer hbuf[0][o_g]
    const uint32_t pdst1 = ph0 + 304u * 4u + (uint32_t)o_g * 4u; // peer hbuf[1][o_g]

    // ONE full cluster sync: init (hbuf + flag) visible cluster-wide
    asm volatile("barrier.cluster.arrive.aligned;" ::: "memory");
    asm volatile("barrier.cluster.wait.aligned;"   ::: "memory");

    const float* uxp = g_ux + (size_t)b * TT * HH;
    float hn  = 0.f;
    float uxv = active ? __ldg(uxp + o_g) : 0.f;   // step 0 prefetched

    for (int step = 0; step < TT; step++) {
        const int cb = step & 1;
        const float* hp = &hbuf[cb][0];

        // ---- Phase A: local k-range (written by own CTA last step) ----
        u64 a01 = 0ull, a23 = 0ull;
        {
            const double2* h2 = (const double2*)(hp + wLbase);
#pragma unroll
            for (int j = 0; j < 19; j++) {
                double2 hv = h2[j];
                FMA_F32X2(a01, wl2[2*j],     d2u_lo(hv));
                FMA_F32X2(a23, wl2[2*j + 1], d2u_hi(hv));
            }
        }

        // prefetch next step's ux (independent)
        float uxn = 0.f;
        if (active && step + 1 < TT)
            uxn = __ldg(uxp + (size_t)(step + 1) * HH + o_g);

        // ---- spin until peer delivered its half of buffer cb ----
        // (flag is monotonic: peer sets it to s+1 at end of its step s)
        {
            unsigned int v;
            do {
                asm volatile("ld.acquire.cluster.shared::cta.b32 %0, [%1];"
                             : "=r"(v) : "r"(my_fl) : "memory");
            } while (v < (unsigned int)step);
        }

        // ---- Phase B: peer k-range ----
        {
            const double2* h2 = (const double2*)(hp + wPbase);
#pragma unroll
            for (int j = 0; j < 19; j++) {
                double2 hv = h2[j];
                FMA_F32X2(a01, wp2[2*j],     d2u_lo(hv));
                FMA_F32X2(a23, wp2[2*j + 1], d2u_hi(hv));
            }
        }
        float f0, f1, f2, f3;
        UNPACK_F32X2(f0, f1, a01);
        UNPACK_F32X2(f2, f3, a23);
        float acc = (f0 + f1) + (f2 + f3);
        acc += __shfl_xor_sync(0xffffffffu, acc, 1);   // combine k-halves

        const int nb = cb ^ 1;
        if (active && half == 0) {
            hn = tanhf(acc + uxv);
            hbuf[nb][o_g] = hn;                         // local copy
            if (step + 1 < TT) {
                const uint32_t pdst = nb ? pdst1 : pdst0;
                asm volatile("st.shared::cluster.f32 [%0], %1;"
                             :: "r"(pdst), "f"(hn) : "memory");
            }
        }
        __syncthreads();    // local stores visible CTA-wide; all threads'
                            // remote stores happen-before t0's release
        if (t == 0 && step + 1 < TT) {
            asm volatile("st.release.cluster.shared::cluster.b32 [%0], %1;"
                         :: "r"(pfl), "r"((unsigned int)(step + 1)) : "memory");
        }
        uxv = uxn;
    }

    if (active && half == 0) g_h[b * HH + o_g] = hn;

    // Exit fence: no CTA leaves while peer may still touch our SMEM
    asm volatile("barrier.cluster.arrive.aligned;" ::: "memory");
    asm volatile("barrier.cluster.wait.aligned;"   ::: "memory");
}

// =====================================================================
// Kernel 3: logits[b][v] = sum_h g_h[b][h] * Wout[v][h] + bout[v]
// CTA: 128 v x 64 b. Thread: 4 v x 8 b. Tk = 8, double-buffered,
// 1 sync/iter, fp32x2 packed FMA.
// =====================================================================
__global__ void __launch_bounds__(256) k_logits(
    const float* __restrict__ Wout, const float* __restrict__ bout,
    float* __restrict__ out)
{
    __shared__ __align__(16) float hs[2][8][68];    // hs[buf][k][b]
    __shared__ __align__(16) float ws[2][8][132];   // ws[buf][k][v_local]

    const int t  = threadIdx.x;
    const int v0 = blockIdx.x * 128;
    const int tx = t & 31;
    const int ty = t >> 5;

    u64 acc2[8][2];   // [b_i][v_pair]
#pragma unroll
    for (int i = 0; i < 8; i++)
#pragma unroll
        for (int p = 0; p < 2; p++) acc2[i][p] = 0ull;

    const int lb   = t & 63;
    const int kq   = t >> 6;
    const int lv   = t & 127;
    const int part = t >> 7;
    const int vg   = v0 + lv;
    const bool vok = (vg < VV);

    const int NIT = 38;

    float2 hv; float4 wv;
    {
        const int k1 = kq * 2;
        hv = *(const float2*)(g_h + lb * HH + k1);
        const int kk = part * 4;
        wv = vok ? *(const float4*)(Wout + (size_t)vg * HH + kk)
                 : make_float4(0.f,0.f,0.f,0.f);
        hs[0][kq*2+0][lb] = hv.x; hs[0][kq*2+1][lb] = hv.y;
        ws[0][part*4+0][lv] = wv.x; ws[0][part*4+1][lv] = wv.y;
        ws[0][part*4+2][lv] = wv.z; ws[0][part*4+3][lv] = wv.w;
    }

    for (int it = 0; it < NIT; it++) {
        __syncthreads();

        if (it + 1 < NIT) {
            const int k0 = (it + 1) * 8;
            const int k1 = k0 + kq * 2;
            hv = (k1 <= HH - 2) ? *(const float2*)(g_h + lb * HH + k1)
                                : make_float2(0.f, 0.f);
            const int kk = k0 + part * 4;
            wv = (vok && kk <= HH - 4)
                     ? *(const float4*)(Wout + (size_t)vg * HH + kk)
                     : make_float4(0.f,0.f,0.f,0.f);
        }

        const int cb = it & 1;
#pragma unroll
        for (int k = 0; k < 8; k++) {
            double2 wd = *(const double2*)&ws[cb][k][tx * 4];  // 2 v-pairs
            const u64 w01 = d2u_lo(wd), w23 = d2u_hi(wd);
            float4 h0 = *(const float4*)&hs[cb][k][ty * 8];
            float4 h1 = *(const float4*)&hs[cb][k][ty * 8 + 4];
            float hr[8] = {h0.x, h0.y, h0.z, h0.w, h1.x, h1.y, h1.z, h1.w};
#pragma unroll
            for (int i = 0; i < 8; i++) {
                u64 hd;
                PACK_F32X2(hd, hr[i], hr[i]);
                FMA_F32X2(acc2[i][0], hd, w01);
                FMA_F32X2(acc2[i][1], hd, w23);
            }
        }

        if (it + 1 < NIT) {
            const int nbuf = (it + 1) & 1;
            hs[nbuf][kq*2+0][lb] = hv.x; hs[nbuf][kq*2+1][lb] = hv.y;
            ws[nbuf][part*4+0][lv] = wv.x; ws[nbuf][part*4+1][lv] = wv.y;
            ws[nbuf][part*4+2][lv] = wv.z; ws[nbuf][part*4+3][lv] = wv.w;
        }
    }

    float bo[4];
#pragma unroll
    for (int j = 0; j < 4; j++) {
        const int v = v0 + tx * 4 + j;
        bo[j] = (v < VV) ? bout[v] : 0.f;
    }
#pragma unroll
    for (int i = 0; i < 8; i++) {
        const int bb = ty * 8 + i;
        float e0, e1, e2, e3;
        UNPACK_F32X2(e0, e1, acc2[i][0]);
        UNPACK_F32X2(e2, e3, acc2[i][1]);
        float ev[4] = {e0, e1, e2, e3};
#pragma unroll
        for (int j = 0; j < 4; j++) {
            const int v = v0 + tx * 4 + j;
            if (v < VV) out[(size_t)bb * VV + v] = ev[j] + bo[j];
        }
    }
}

// =====================================================================
extern "C" void kernel_launch(void* const* d_in, const int* in_sizes, int n_in,
                              void* d_out, int out_size)
{
    const float* ihs  = (const float*)d_in[0];
    const int*   tok  = (const int*)  d_in[1];
    const float* emb  = (const float*)d_in[2];
    const float* W    = (const float*)d_in[3];
    const float* U    = (const float*)d_in[4];
    const float* Wout = (const float*)d_in[5];
    const float* bout = (const float*)d_in[6];
    float* out = (float*)d_out;

    k_embed_ux<<<dim3((BB * TT) / 128, 3), 256>>>(tok, emb, U);
    k_scan<<<BB * 2, 320>>>(W, ihs);
    k_logits<<<(VV + 127) / 128, 256>>>(Wout, bout, out);
}

// round 15
// speedup vs baseline: 1.1759x; 1.1759x over previous
#include <cuda_runtime.h>
#include <cuda_bf16.h>
#include <cstdint>

#define BB 64
#define TT 512
#define HH 300
#define VV 50257

// Scratch (allocation-free: __device__ globals)
__device__ float g_ux[BB * TT * HH];   // [B*T, H] input projections
__device__ float g_h[BB * HH];         // final hidden state

// ---- smem layout for k1 (bf16 tiles, pitch 72 cols = 144 B) ----
#define PITCH_B 144
#define AH_OFF 0
#define AL_OFF 18432            // 128*144
#define BH_OFF 36864
#define BL_OFF 80640            // 36864 + 304*144
#define K1_BYTES (124416 + 128) // + alignment pad

__device__ __forceinline__ void mma16816(float* c, const uint32_t* a,
                                         uint32_t b0, uint32_t b1) {
    asm volatile(
        "mma.sync.aligned.m16n8k16.row.col.f32.bf16.bf16.f32 "
        "{%0,%1,%2,%3}, {%4,%5,%6,%7}, {%8,%9}, {%0,%1,%2,%3};"
        : "+f"(c[0]), "+f"(c[1]), "+f"(c[2]), "+f"(c[3])
        : "r"(a[0]), "r"(a[1]), "r"(a[2]), "r"(a[3]), "r"(b0), "r"(b1));
}

__device__ __forceinline__ uint32_t pack_bf16(float a, float b) {
    __nv_bfloat162 h = __floats2bfloat162_rn(a, b);
    return *reinterpret_cast<uint32_t*>(&h);
}

// =====================================================================
// Kernel 1 (HMMA): ux[m,g] = sum_h emb[tokens[m]][h] * U[g][h]
// bf16 3-split (hh + lh + hl) on mma.sync m16n8k16, fp32 accumulate.
// CTA: 256 thr / 8 warps; M=128 tokens, N=304 (38 n-tiles), K=5x64.
// U is [g][h] row-major == B^T row-major, which is what row.col wants.
// =====================================================================
__global__ void __launch_bounds__(256, 1) k_embed_ux_mma(
    const int* __restrict__ tokens, const float* __restrict__ emb,
    const float* __restrict__ U)
{
    extern __shared__ char dsm_raw[];
    __shared__ int ts[128];

    const int t    = threadIdx.x;
    const int w    = t >> 5;
    const int lane = t & 31;
    const int r    = lane >> 2;   // groupID
    const int tig  = lane & 3;    // thread-in-group
    const int m0   = blockIdx.x * 128;

    // align dynamic smem base to 128 B (keeps the bank proof valid)
    uintptr_t rawp = (uintptr_t)dsm_raw;
    char* dsm = dsm_raw + (((rawp + 127u) & ~(uintptr_t)127u) - rawp);

    if (t < 128) ts[t] = tokens[m0 + t];

    float acc[38][4];
#pragma unroll
    for (int nt = 0; nt < 38; nt++)
#pragma unroll
        for (int j = 0; j < 4; j++) acc[nt][j] = 0.f;

    for (int c = 0; c < 5; c++) {
        const int k0 = c * 64;
        __syncthreads();   // previous chunk's readers done

        // ---- fill A tiles (gathered emb rows 0..127, cols k0..k0+63) ----
        for (int idx = t; idx < 128 * 16; idx += 256) {
            const int row  = idx >> 4;
            const int c4   = idx & 15;
            const int gcol = k0 + c4 * 4;
            float4 v = make_float4(0.f, 0.f, 0.f, 0.f);
            if (gcol <= HH - 4)
                v = *(const float4*)(emb + (size_t)ts[row] * HH + gcol);
            float h0 = __bfloat162float(__float2bfloat16_rn(v.x));
            float h1 = __bfloat162float(__float2bfloat16_rn(v.y));
            float h2 = __bfloat162float(__float2bfloat16_rn(v.z));
            float h3 = __bfloat162float(__float2bfloat16_rn(v.w));
            uint2 hi = make_uint2(pack_bf16(h0, h1), pack_bf16(h2, h3));
            uint2 lo = make_uint2(pack_bf16(v.x - h0, v.y - h1),
                                  pack_bf16(v.z - h2, v.w - h3));
            const int off = row * PITCH_B + c4 * 8;
            *(uint2*)(dsm + AH_OFF + off) = hi;
            *(uint2*)(dsm + AL_OFF + off) = lo;
        }
        // ---- fill B tiles (U rows 0..303, cols k0..k0+63) ----
        for (int idx = t; idx < 304 * 16; idx += 256) {
            const int row  = idx >> 4;
            const int c4   = idx & 15;
            const int gcol = k0 + c4 * 4;
            float4 v = make_float4(0.f, 0.f, 0.f, 0.f);
            if (row < HH && gcol <= HH - 4)
                v = *(const float4*)(U + (size_t)row * HH + gcol);
            float h0 = __bfloat162float(__float2bfloat16_rn(v.x));
            float h1 = __bfloat162float(__float2bfloat16_rn(v.y));
            float h2 = __bfloat162float(__float2bfloat16_rn(v.z));
            float h3 = __bfloat162float(__float2bfloat16_rn(v.w));
            uint2 hi = make_uint2(pack_bf16(h0, h1), pack_bf16(h2, h3));
            uint2 lo = make_uint2(pack_bf16(v.x - h0, v.y - h1),
                                  pack_bf16(v.z - h2, v.w - h3));
            const int off = row * PITCH_B + c4 * 8;
            *(uint2*)(dsm + BH_OFF + off) = hi;
            *(uint2*)(dsm + BL_OFF + off) = lo;
        }
        __syncthreads();

        // ---- compute: 4 k16-steps x 38 n-tiles x 3 split-mmas ----
#pragma unroll
        for (int ks = 0; ks < 4; ks++) {
            const int koff = ks * 32 + tig * 4;   // byte offset: k = ks*16 + 2*tig
            const int arow = (w * 16 + r) * PITCH_B;
            uint32_t ah[4], al[4];
            ah[0] = *(const uint32_t*)(dsm + AH_OFF + arow + koff);
            ah[1] = *(const uint32_t*)(dsm + AH_OFF + arow + 8 * PITCH_B + koff);
            ah[2] = *(const uint32_t*)(dsm + AH_OFF + arow + koff + 16);
            ah[3] = *(const uint32_t*)(dsm + AH_OFF + arow + 8 * PITCH_B + koff + 16);
            al[0] = *(const uint32_t*)(dsm + AL_OFF + arow + koff);
            al[1] = *(const uint32_t*)(dsm + AL_OFF + arow + 8 * PITCH_B + koff);
            al[2] = *(const uint32_t*)(dsm + AL_OFF + arow + koff + 16);
            al[3] = *(const uint32_t*)(dsm + AL_OFF + arow + 8 * PITCH_B + koff + 16);
#pragma unroll
            for (int nt = 0; nt < 38; nt++) {
                const int brow = (nt * 8 + r) * PITCH_B;
                uint32_t bh0 = *(const uint32_t*)(dsm + BH_OFF + brow + koff);
                uint32_t bh1 = *(const uint32_t*)(dsm + BH_OFF + brow + koff + 16);
                uint32_t bl0 = *(const uint32_t*)(dsm + BL_OFF + brow + koff);
                uint32_t bl1 = *(const uint32_t*)(dsm + BL_OFF + brow + koff + 16);
                mma16816(acc[nt], ah, bh0, bh1);   // hi*hi
                mma16816(acc[nt], al, bh0, bh1);   // lo*hi
                mma16816(acc[nt], ah, bl0, bl1);   // hi*lo
            }
        }
    }

    // ---- epilogue: c-frag mapping -> g_ux ----
    const int row0 = m0 + w * 16 + r;
#pragma unroll
    for (int nt = 0; nt < 38; nt++) {
        const int col = nt * 8 + 2 * tig;
        if (col < HH) {
            *(float2*)(g_ux + (size_t)row0 * HH + col) =
                make_float2(acc[nt][0], acc[nt][1]);
            *(float2*)(g_ux + (size_t)(row0 + 8) * HH + col) =
                make_float2(acc[nt][2], acc[nt][3]);
        }
    }
}

// =====================================================================
// Kernel 2: recurrence (R6-proven, byte-identical).  2-CTA cluster per
// batch element; monotonic DSMEM flag handshake.
// =====================================================================
__global__ void __launch_bounds__(320, 1) __cluster_dims__(2, 1, 1)
k_scan(const float* __restrict__ W, const float* __restrict__ ihs)
{
    __shared__ float hbuf[2][304];
    __shared__ unsigned int flag;

    const int t    = threadIdx.x;
    const int r    = blockIdx.x & 1;
    const int b    = blockIdx.x >> 1;
    const int o_l  = t >> 1;
    const int half = t & 1;

    const int Lb     = r ? 152 : 0;
    const int Pb     = r ? 0 : 152;
    const int myLen  = r ? 148 : 152;
    const bool active = (o_l < myLen);
    const int o_g    = Lb + o_l;

    const int wLbase = Lb + half * 76;
    const int wPbase = Pb + half * 76;

    float wl[76], wp[76];
#pragma unroll
    for (int j = 0; j < 76; j++) {
        const int kL = wLbase + j;
        const int kP = wPbase + j;
        wl[j] = (active && kL < HH) ? W[(size_t)o_g * HH + kL] : 0.f;
        wp[j] = (active && kP < HH) ? W[(size_t)o_g * HH + kP] : 0.f;
    }

    if (t < 304) {
        hbuf[0][t] = (t < HH) ? ihs[b * HH + t] : 0.f;
        hbuf[1][t] = 0.f;
    }
    if (t == 0) flag = 0u;

    uint32_t my_h0, my_fl;
    {
        uint64_t a;
        asm("cvta.to.shared.u64 %0, %1;" : "=l"(a) : "l"(&hbuf[0][0]));
        my_h0 = (uint32_t)a;
        asm("cvta.to.shared.u64 %0, %1;" : "=l"(a) : "l"(&flag));
        my_fl = (uint32_t)a;
    }
    uint32_t ph0, pfl;
    asm("mapa.shared::cluster.u32 %0, %1, %2;" : "=r"(ph0) : "r"(my_h0), "r"(r ^ 1));
    asm("mapa.shared::cluster.u32 %0, %1, %2;" : "=r"(pfl) : "r"(my_fl), "r"(r ^ 1));
    const uint32_t pdst0 = ph0 + (uint32_t)o_g * 4u;
    const uint32_t pdst1 = ph0 + 304u * 4u + (uint32_t)o_g * 4u;

    asm volatile("barrier.cluster.arrive.aligned;" ::: "memory");
    asm volatile("barrier.cluster.wait.aligned;"   ::: "memory");

    const float* uxp = g_ux + (size_t)b * TT * HH;
    float hn  = 0.f;
    float uxv = active ? __ldg(uxp + o_g) : 0.f;

    for (int step = 0; step < TT; step++) {
        const int cb = step & 1;
        const float* hp = &hbuf[cb][0];

        float a0 = 0.f, a1 = 0.f, a2 = 0.f, a3 = 0.f;
        const float* hl = hp + wLbase;
#pragma unroll
        for (int j = 0; j < 76; j += 4) {
            float4 hv = *(const float4*)(hl + j);
            a0 = fmaf(wl[j + 0], hv.x, a0);
            a1 = fmaf(wl[j + 1], hv.y, a1);
            a2 = fmaf(wl[j + 2], hv.z, a2);
            a3 = fmaf(wl[j + 3], hv.w, a3);
        }

        float uxn = 0.f;
        if (active && step + 1 < TT)
            uxn = __ldg(uxp + (size_t)(step + 1) * HH + o_g);

        {
            unsigned int v;
            do {
                asm volatile("ld.acquire.cluster.shared::cta.b32 %0, [%1];"
                             : "=r"(v) : "r"(my_fl) : "memory");
            } while (v < (unsigned int)step);
        }

        const float* hq = hp + wPbase;
#pragma unroll
        for (int j = 0; j < 76; j += 4) {
            float4 hv = *(const float4*)(hq + j);
            a0 = fmaf(wp[j + 0], hv.x, a0);
            a1 = fmaf(wp[j + 1], hv.y, a1);
            a2 = fmaf(wp[j + 2], hv.z, a2);
            a3 = fmaf(wp[j + 3], hv.w, a3);
        }
        float acc = (a0 + a1) + (a2 + a3);
        acc += __shfl_xor_sync(0xffffffffu, acc, 1);

        const int nb = cb ^ 1;
        if (active && half == 0) {
            hn = tanhf(acc + uxv);
            hbuf[nb][o_g] = hn;
            if (step + 1 < TT) {
                const uint32_t pdst = nb ? pdst1 : pdst0;
                asm volatile("st.shared::cluster.f32 [%0], %1;"
                             :: "r"(pdst), "f"(hn) : "memory");
            }
        }
        __syncthreads();
        if (t == 0 && step + 1 < TT) {
            asm volatile("st.release.cluster.shared::cluster.b32 [%0], %1;"
                         :: "r"(pfl), "r"((unsigned int)(step + 1)) : "memory");
        }
        uxv = uxn;
    }

    if (active && half == 0) g_h[b * HH + o_g] = hn;

    asm volatile("barrier.cluster.arrive.aligned;" ::: "memory");
    asm volatile("barrier.cluster.wait.aligned;"   ::: "memory");
}

// =====================================================================
// Kernel 3: logits (R6-proven, byte-identical).
// =====================================================================
__global__ void __launch_bounds__(256) k_logits(
    const float* __restrict__ Wout, const float* __restrict__ bout,
    float* __restrict__ out)
{
    __shared__ float hs[2][8][68];
    __shared__ float ws[2][8][132];

    const int t  = threadIdx.x;
    const int v0 = blockIdx.x * 128;
    const int tx = t & 31;
    const int ty = t >> 5;

    float acc[8][4];
#pragma unroll
    for (int i = 0; i < 8; i++)
#pragma unroll
        for (int j = 0; j < 4; j++) acc[i][j] = 0.f;

    const int lb   = t & 63;
    const int kq   = t >> 6;
    const int lv   = t & 127;
    const int part = t >> 7;
    const int vg   = v0 + lv;
    const bool vok = (vg < VV);

    const int NIT = 38;

    float2 hv; float4 wv;
    {
        const int k1 = kq * 2;
        hv = *(const float2*)(g_h + lb * HH + k1);
        const int kk = part * 4;
        wv = vok ? *(const float4*)(Wout + (size_t)vg * HH + kk)
                 : make_float4(0.f,0.f,0.f,0.f);
        hs[0][kq*2+0][lb] = hv.x; hs[0][kq*2+1][lb] = hv.y;
        ws[0][part*4+0][lv] = wv.x; ws[0][part*4+1][lv] = wv.y;
        ws[0][part*4+2][lv] = wv.z; ws[0][part*4+3][lv] = wv.w;
    }

    for (int it = 0; it < NIT; it++) {
        __syncthreads();

        if (it + 1 < NIT) {
            const int k0 = (it + 1) * 8;
            const int k1 = k0 + kq * 2;
            hv = (k1 <= HH - 2) ? *(const float2*)(g_h + lb * HH + k1)
                                : make_float2(0.f, 0.f);
            const int kk = k0 + part * 4;
            wv = (vok && kk <= HH - 4)
                     ? *(const float4*)(Wout + (size_t)vg * HH + kk)
                     : make_float4(0.f,0.f,0.f,0.f);
        }

        const int cb = it & 1;
#pragma unroll
        for (int k = 0; k < 8; k++) {
            float4 wr = *(const float4*)&ws[cb][k][tx * 4];
            float4 h0 = *(const float4*)&hs[cb][k][ty * 8];
            float4 h1 = *(const float4*)&hs[cb][k][ty * 8 + 4];
            float hr[8] = {h0.x, h0.y, h0.z, h0.w, h1.x, h1.y, h1.z, h1.w};
            float vr[4] = {wr.x, wr.y, wr.z, wr.w};
#pragma unroll
            for (int i = 0; i < 8; i++)
#pragma unroll
                for (int j = 0; j < 4; j++)
                    acc[i][j] = fmaf(hr[i], vr[j], acc[i][j]);
        }

        if (it + 1 < NIT) {
            const int nbuf = (it + 1) & 1;
            hs[nbuf][kq*2+0][lb] = hv.x; hs[nbuf][kq*2+1][lb] = hv.y;
            ws[nbuf][part*4+0][lv] = wv.x; ws[nbuf][part*4+1][lv] = wv.y;
            ws[nbuf][part*4+2][lv] = wv.z; ws[nbuf][part*4+3][lv] = wv.w;
        }
    }

    float bo[4];
#pragma unroll
    for (int j = 0; j < 4; j++) {
        const int v = v0 + tx * 4 + j;
        bo[j] = (v < VV) ? bout[v] : 0.f;
    }
#pragma unroll
    for (int i = 0; i < 8; i++) {
        const int bb = ty * 8 + i;
#pragma unroll
        for (int j = 0; j < 4; j++) {
            const int v = v0 + tx * 4 + j;
            if (v < VV) out[(size_t)bb * VV + v] = acc[i][j] + bo[j];
        }
    }
}

// =====================================================================
extern "C" void kernel_launch(void* const* d_in, const int* in_sizes, int n_in,
                              void* d_out, int out_size)
{
    const float* ihs  = (const float*)d_in[0];
    const int*   tok  = (const int*)  d_in[1];
    const float* emb  = (const float*)d_in[2];
    const float* W    = (const float*)d_in[3];
    const float* U    = (const float*)d_in[4];
    const float* Wout = (const float*)d_in[5];
    const float* bout = (const float*)d_in[6];
    float* out = (float*)d_out;

    cudaFuncSetAttribute(k_embed_ux_mma,
                         cudaFuncAttributeMaxDynamicSharedMemorySize, K1_BYTES);

    k_embed_ux_mma<<<(BB * TT) / 128, 256, K1_BYTES>>>(tok, emb, U);
    k_scan<<<BB * 2, 320>>>(W, ihs);
    k_logits<<<(VV + 127) / 128, 256>>>(Wout, bout, out);
}